// round 1
// baseline (speedup 1.0000x reference)
#include <cuda_runtime.h>
#include <math.h>

#define NN 20000
#define NE 640000
#define D  128

// ---------------- static device scratch (no allocations allowed) ----------------
__device__ float g_qhat[NN * D];     // query_node @ (Wq @ Wk^T)
__device__ float g_agg[NN * D];      // segment_sum(attn * value_edge)
__device__ float g_proj[NN * D];     // g_agg @ (Wv @ Wo)
__device__ float g_scores[NE];
__device__ int   g_deg[NN];
__device__ int   g_off[NN + 1];
__device__ int   g_cur[NN];
__device__ int   g_eids[NE];
__device__ float g_Wc[D * D];        // Wq @ Wk^T
__device__ float g_W2[D * D];        // Wv @ Wo

// ---------------- zero counters ----------------
__global__ void zero_counts_kernel() {
    int i = blockIdx.x * blockDim.x + threadIdx.x;
    if (i < NN) { g_deg[i] = 0; g_cur[i] = 0; }
}

// ---------------- combine weight matrices ----------------
// Wc[a][b] = sum_j Wq[a][j] * Wk[b][j]      (Wq @ Wk^T)
// W2[a][b] = sum_j Wv[a][j] * Wo[j][b]      (Wv @ Wo)
__global__ void combine_w_kernel(const float* __restrict__ Wq,
                                 const float* __restrict__ Wk,
                                 const float* __restrict__ Wv,
                                 const float* __restrict__ Wo) {
    int a = blockIdx.x;
    int b = threadIdx.x;
    float c1 = 0.f, c2 = 0.f;
#pragma unroll 8
    for (int j = 0; j < D; j++) {
        c1 = fmaf(Wq[a * D + j], Wk[b * D + j], c1);
        c2 = fmaf(Wv[a * D + j], Wo[j * D + b], c2);
    }
    g_Wc[a * D + b] = c1;
    g_W2[a * D + b] = c2;
}

// ---------------- tiled fp32 GEMM: C[M,128] = A[M,128] @ B[128,128] ----------------
// whichB: 0 -> g_Wc, 1 -> g_W2. 256 threads/block, 64 rows/block, 48KB smem.
__global__ void gemm_tiled_kernel(const float* __restrict__ A, int M, int whichB,
                                  float* __restrict__ C) {
    __shared__ float As[64][D];      // 32 KB
    __shared__ float Bs[D][32];      // 16 KB
    const float* B = whichB ? g_W2 : g_Wc;
    int rb = blockIdx.x * 64;
    int t  = threadIdx.x;

    const float4* A4 = reinterpret_cast<const float4*>(A);
#pragma unroll
    for (int i = 0; i < 8; i++) {
        int lin = i * 256 + t;          // 0..2047 float4 slots
        int r   = lin >> 5;             // 32 float4 per row
        int c4  = lin & 31;
        float4 v = make_float4(0.f, 0.f, 0.f, 0.f);
        if (rb + r < M) v = A4[(size_t)(rb + r) * 32 + c4];
        reinterpret_cast<float4*>(&As[r][0])[c4] = v;
    }

    int col = t & 31;
    int rb8 = (t >> 5) * 8;

    for (int ct = 0; ct < 4; ct++) {
        __syncthreads();   // protects As on first iter, Bs reuse on later iters
#pragma unroll
        for (int i = 0; i < 16; i++) {
            int lin = i * 256 + t;      // 0..4095
            int k   = lin >> 5;
            int c   = lin & 31;
            Bs[k][c] = B[k * D + ct * 32 + c];
        }
        __syncthreads();

        float acc[8] = {0.f, 0.f, 0.f, 0.f, 0.f, 0.f, 0.f, 0.f};
#pragma unroll 4
        for (int kk = 0; kk < D; kk++) {
            float b = Bs[kk][col];
#pragma unroll
            for (int r = 0; r < 8; r++)
                acc[r] = fmaf(As[rb8 + r][kk], b, acc[r]);
        }
#pragma unroll
        for (int r = 0; r < 8; r++) {
            int row = rb + rb8 + r;
            if (row < M) C[(size_t)row * D + ct * 32 + col] = acc[r];
        }
    }
}

// ---------------- per-edge scores + degree count (warp per edge) ----------------
__global__ void scores_kernel(const float* __restrict__ key_edge,
                              const int* __restrict__ tgt) {
    int w = (blockIdx.x * blockDim.x + threadIdx.x) >> 5;
    if (w >= NE) return;
    int lane = threadIdx.x & 31;
    int t = tgt[w];
    float4 kv = reinterpret_cast<const float4*>(key_edge)[(size_t)w * 32 + lane];
    float4 qv = reinterpret_cast<const float4*>(g_qhat)[(size_t)t * 32 + lane];
    float d = kv.x * qv.x + kv.y * qv.y + kv.z * qv.z + kv.w * qv.w;
#pragma unroll
    for (int o = 16; o; o >>= 1) d += __shfl_xor_sync(0xffffffffu, d, o);
    if (lane == 0) {
        g_scores[w] = d * 0.08838834764831845f;   // 128^-0.5
        atomicAdd(&g_deg[t], 1);
    }
}

// ---------------- single-block exclusive scan over degrees ----------------
__global__ void scan_kernel() {
    __shared__ int sh[1024];
    __shared__ int carry;
    if (threadIdx.x == 0) carry = 0;
    __syncthreads();
    for (int base = 0; base < NN; base += 1024) {
        int i = base + threadIdx.x;
        int v = (i < NN) ? g_deg[i] : 0;
        sh[threadIdx.x] = v;
        __syncthreads();
        for (int s = 1; s < 1024; s <<= 1) {
            int t = (threadIdx.x >= s) ? sh[threadIdx.x - s] : 0;
            __syncthreads();
            sh[threadIdx.x] += t;
            __syncthreads();
        }
        int incl = sh[threadIdx.x] + carry;
        if (i < NN) g_off[i + 1] = incl;
        __syncthreads();
        if (threadIdx.x == 1023) carry = incl;
        __syncthreads();
    }
    if (threadIdx.x == 0) g_off[0] = 0;
}

// ---------------- scatter edge ids into CSR ----------------
__global__ void scatter_kernel(const int* __restrict__ tgt) {
    int e = blockIdx.x * blockDim.x + threadIdx.x;
    if (e >= NE) return;
    int t = tgt[e];
    int p = atomicAdd(&g_cur[t], 1);
    g_eids[g_off[t] + p] = e;
}

// ---------------- per-node softmax + weighted value aggregation (warp per node) ----------------
__global__ void node_kernel(const float* __restrict__ value,
                            float* __restrict__ attn_out) {
    int n = (blockIdx.x << 3) + (threadIdx.x >> 5);
    if (n >= NN) return;
    int lane = threadIdx.x & 31;
    int s0 = g_off[n], s1 = g_off[n + 1];

    float m = -INFINITY;
    for (int i = s0 + lane; i < s1; i += 32) m = fmaxf(m, g_scores[g_eids[i]]);
#pragma unroll
    for (int o = 16; o; o >>= 1) m = fmaxf(m, __shfl_xor_sync(0xffffffffu, m, o));

    float ss = 0.f;
    for (int i = s0 + lane; i < s1; i += 32) ss += expf(g_scores[g_eids[i]] - m);
#pragma unroll
    for (int o = 16; o; o >>= 1) ss += __shfl_xor_sync(0xffffffffu, ss, o);
    float inv = 1.f / (ss + 1e-12f);

    float4 acc = make_float4(0.f, 0.f, 0.f, 0.f);
    const float4* V4 = reinterpret_cast<const float4*>(value);
    for (int i = s0; i < s1; i++) {
        int eid = g_eids[i];                       // uniform across warp -> broadcast
        float w = expf(g_scores[eid] - m) * inv;
        if (attn_out != nullptr && lane == 0) attn_out[eid] = w;
        float4 v = V4[(size_t)eid * 32 + lane];
        acc.x = fmaf(w, v.x, acc.x);
        acc.y = fmaf(w, v.y, acc.y);
        acc.z = fmaf(w, v.z, acc.z);
        acc.w = fmaf(w, v.w, acc.w);
    }
    reinterpret_cast<float4*>(g_agg)[(size_t)n * 32 + lane] = acc;
}

// ---------------- bias + LayerNorm ----------------
__global__ void ln_kernel(const float* __restrict__ bo,
                          const float* __restrict__ gamma,
                          const float* __restrict__ beta,
                          float* __restrict__ out) {
    int n = blockIdx.x;
    int j = threadIdx.x;
    int lane = j & 31, wid = j >> 5;
    __shared__ float red[4];

    float p = g_proj[n * D + j] + bo[j];
    float s = p;
#pragma unroll
    for (int o = 16; o; o >>= 1) s += __shfl_xor_sync(0xffffffffu, s, o);
    if (lane == 0) red[wid] = s;
    __syncthreads();
    float mu = (red[0] + red[1] + red[2] + red[3]) * (1.f / 128.f);
    float d = p - mu;
    float q = d * d;
    __syncthreads();
#pragma unroll
    for (int o = 16; o; o >>= 1) q += __shfl_xor_sync(0xffffffffu, q, o);
    if (lane == 0) red[wid] = q;
    __syncthreads();
    float var = (red[0] + red[1] + red[2] + red[3]) * (1.f / 128.f);
    out[n * D + j] = d * rsqrtf(var + 1e-5f) * gamma[j] + beta[j];
}

// ---------------- launch ----------------
extern "C" void kernel_launch(void* const* d_in, const int* in_sizes, int n_in,
                              void* d_out, int out_size) {
    const float* qn    = (const float*)d_in[0];   // [NN, 128]
    const float* ke    = (const float*)d_in[1];   // [NE, 128]
    const float* ve    = (const float*)d_in[2];   // [NE, 128]
    const int*   ei    = (const int*)  d_in[3];   // [2, NE]
    const float* Wq    = (const float*)d_in[4];
    const float* Wk    = (const float*)d_in[5];
    const float* Wv    = (const float*)d_in[6];
    const float* Wo    = (const float*)d_in[7];
    const float* bo    = (const float*)d_in[8];
    const float* gamma = (const float*)d_in[9];
    const float* beta  = (const float*)d_in[10];

    const int* tgt = ei + NE;                     // edge_index[1]
    float* out = (float*)d_out;
    float* attn = (out_size >= NN * D + NE) ? (out + NN * D) : nullptr;

    float *p_qhat = nullptr, *p_agg = nullptr, *p_proj = nullptr;
    cudaGetSymbolAddress((void**)&p_qhat, g_qhat);
    cudaGetSymbolAddress((void**)&p_agg,  g_agg);
    cudaGetSymbolAddress((void**)&p_proj, g_proj);

    zero_counts_kernel<<<(NN + 255) / 256, 256>>>();
    combine_w_kernel<<<D, D>>>(Wq, Wk, Wv, Wo);
    gemm_tiled_kernel<<<(NN + 63) / 64, 256>>>(qn, NN, 0, p_qhat);
    scores_kernel<<<NE / 8, 256>>>(ke, tgt);      // warp per edge, 8 warps/block
    scan_kernel<<<1, 1024>>>();
    scatter_kernel<<<(NE + 255) / 256, 256>>>(tgt);
    node_kernel<<<(NN + 7) / 8, 256>>>(ve, attn);
    gemm_tiled_kernel<<<(NN + 63) / 64, 256>>>(p_agg, NN, 1, p_proj);
    ln_kernel<<<NN, 128>>>(bo, gamma, beta, out);
}

// round 2
// speedup vs baseline: 1.2000x; 1.2000x over previous
#include <cuda_runtime.h>
#include <math.h>

#define NN 20000
#define NE 640000
#define D  128

// ---------------- static device scratch ----------------
__device__ float g_qhat[NN * D];     // query_node @ (Wq @ Wk^T)
__device__ float g_agg[NN * D];      // segment_sum(attn * value_edge)
__device__ float g_proj[NN * D];     // g_agg @ (Wv @ Wo)
__device__ float g_scores[NE];       // raw scaled scores, edge order
__device__ float g_exp[NE];          // exp(score - m[tgt]), CSR order
__device__ int   g_eids[NE];         // edge ids, CSR order
__device__ int   g_deg[NN];
__device__ int   g_off[NN + 1];
__device__ int   g_cur[NN];
__device__ int   g_max[NN];          // order-encoded float max per node
__device__ float g_Wc[D * D];        // Wq @ Wk^T
__device__ float g_W2[D * D];        // Wv @ Wo

__device__ __forceinline__ int f2ord(float f) {
    int i = __float_as_int(f);
    return i >= 0 ? i : (i ^ 0x7FFFFFFF);
}
__device__ __forceinline__ float ord2f(int i) {
    return __int_as_float(i >= 0 ? i : (i ^ 0x7FFFFFFF));
}

// ---------------- zero counters ----------------
__global__ void zero_counts_kernel() {
    int i = blockIdx.x * blockDim.x + threadIdx.x;
    if (i < NN) { g_deg[i] = 0; g_cur[i] = 0; g_max[i] = 0x80000000; }
}

// ---------------- combine weight matrices ----------------
__global__ void combine_w_kernel(const float* __restrict__ Wq,
                                 const float* __restrict__ Wk,
                                 const float* __restrict__ Wv,
                                 const float* __restrict__ Wo) {
    int a = blockIdx.x;
    int b = threadIdx.x;
    float c1 = 0.f, c2 = 0.f;
#pragma unroll 8
    for (int j = 0; j < D; j++) {
        c1 = fmaf(Wq[a * D + j], Wk[b * D + j], c1);
        c2 = fmaf(Wv[a * D + j], Wo[j * D + b], c2);
    }
    g_Wc[a * D + b] = c1;
    g_W2[a * D + b] = c2;
}

// ---------------- tiled fp32 GEMM: C[M,128] = A[M,128] @ B[128,128] ----------------
__global__ void gemm_tiled_kernel(const float* __restrict__ A, int M, int whichB,
                                  float* __restrict__ C) {
    __shared__ float As[64][D];      // 32 KB
    __shared__ float Bs[D][32];      // 16 KB
    const float* B = whichB ? g_W2 : g_Wc;
    int rb = blockIdx.x * 64;
    int t  = threadIdx.x;

    const float4* A4 = reinterpret_cast<const float4*>(A);
#pragma unroll
    for (int i = 0; i < 8; i++) {
        int lin = i * 256 + t;
        int r   = lin >> 5;
        int c4  = lin & 31;
        float4 v = make_float4(0.f, 0.f, 0.f, 0.f);
        if (rb + r < M) v = A4[(size_t)(rb + r) * 32 + c4];
        reinterpret_cast<float4*>(&As[r][0])[c4] = v;
    }

    int col = t & 31;
    int rb8 = (t >> 5) * 8;

    for (int ct = 0; ct < 4; ct++) {
        __syncthreads();
#pragma unroll
        for (int i = 0; i < 16; i++) {
            int lin = i * 256 + t;
            int k   = lin >> 5;
            int c   = lin & 31;
            Bs[k][c] = B[k * D + ct * 32 + c];
        }
        __syncthreads();

        float acc[8] = {0.f, 0.f, 0.f, 0.f, 0.f, 0.f, 0.f, 0.f};
#pragma unroll 4
        for (int kk = 0; kk < D; kk++) {
            float b = Bs[kk][col];
#pragma unroll
            for (int r = 0; r < 8; r++)
                acc[r] = fmaf(As[rb8 + r][kk], b, acc[r]);
        }
#pragma unroll
        for (int r = 0; r < 8; r++) {
            int row = rb + rb8 + r;
            if (row < M) C[(size_t)row * D + ct * 32 + col] = acc[r];
        }
    }
}

// ---------------- scores: warp handles 4 edges; also degree count + seg max ----------------
__global__ void scores_kernel(const float* __restrict__ key_edge,
                              const int* __restrict__ tgt) {
    int w = (blockIdx.x * blockDim.x + threadIdx.x) >> 5;
    int e0 = w * 4;
    if (e0 >= NE) return;
    int lane = threadIdx.x & 31;

    int t0 = tgt[e0], t1 = tgt[e0 + 1], t2 = tgt[e0 + 2], t3 = tgt[e0 + 3];

    const float4* K4 = reinterpret_cast<const float4*>(key_edge);
    const float4* Q4 = reinterpret_cast<const float4*>(g_qhat);

    float4 k0 = K4[(size_t)(e0 + 0) * 32 + lane];
    float4 k1 = K4[(size_t)(e0 + 1) * 32 + lane];
    float4 k2 = K4[(size_t)(e0 + 2) * 32 + lane];
    float4 k3 = K4[(size_t)(e0 + 3) * 32 + lane];
    float4 q0 = Q4[(size_t)t0 * 32 + lane];
    float4 q1 = Q4[(size_t)t1 * 32 + lane];
    float4 q2 = Q4[(size_t)t2 * 32 + lane];
    float4 q3 = Q4[(size_t)t3 * 32 + lane];

    float d0 = k0.x * q0.x + k0.y * q0.y + k0.z * q0.z + k0.w * q0.w;
    float d1 = k1.x * q1.x + k1.y * q1.y + k1.z * q1.z + k1.w * q1.w;
    float d2 = k2.x * q2.x + k2.y * q2.y + k2.z * q2.z + k2.w * q2.w;
    float d3 = k3.x * q3.x + k3.y * q3.y + k3.z * q3.z + k3.w * q3.w;
#pragma unroll
    for (int o = 16; o; o >>= 1) {
        d0 += __shfl_xor_sync(0xffffffffu, d0, o);
        d1 += __shfl_xor_sync(0xffffffffu, d1, o);
        d2 += __shfl_xor_sync(0xffffffffu, d2, o);
        d3 += __shfl_xor_sync(0xffffffffu, d3, o);
    }
    if (lane < 4) {
        float ds = (lane == 0) ? d0 : (lane == 1) ? d1 : (lane == 2) ? d2 : d3;
        int   ts = (lane == 0) ? t0 : (lane == 1) ? t1 : (lane == 2) ? t2 : t3;
        float sc = ds * 0.08838834764831845f;   // 128^-0.5
        g_scores[e0 + lane] = sc;
        atomicAdd(&g_deg[ts], 1);
        atomicMax(&g_max[ts], f2ord(sc));
    }
}

// ---------------- single-block scan (shuffle-based, 20 elems/thread) ----------------
__global__ void scan_kernel() {
    const int PER = (NN + 1023) / 1024;          // 20
    int t = threadIdx.x;
    int lane = t & 31, wid = t >> 5;
    int base = t * PER;

    int local[PER];
    int s = 0;
#pragma unroll
    for (int j = 0; j < PER; j++) {
        int idx = base + j;
        int v = (idx < NN) ? g_deg[idx] : 0;
        local[j] = s;                             // exclusive within segment
        s += v;
    }
    // inclusive warp scan of s
    int incl = s;
#pragma unroll
    for (int o = 1; o < 32; o <<= 1) {
        int u = __shfl_up_sync(0xffffffffu, incl, o);
        if (lane >= o) incl += u;
    }
    __shared__ int wsum[32];
    if (lane == 31) wsum[wid] = incl;
    __syncthreads();
    if (wid == 0) {
        int v = wsum[lane];
        int wv = v;
#pragma unroll
        for (int o = 1; o < 32; o <<= 1) {
            int u = __shfl_up_sync(0xffffffffu, wv, o);
            if (lane >= o) wv += u;
        }
        wsum[lane] = wv - v;                      // exclusive warp offsets
    }
    __syncthreads();
    int excl = incl - s + wsum[wid];
#pragma unroll
    for (int j = 0; j < PER; j++) {
        int idx = base + j;
        if (idx < NN) g_off[idx] = excl + local[j];
    }
    if (t == 1023) g_off[NN] = excl + s;
}

// ---------------- scatter: CSR-order (eid, exp(score-m)) ----------------
__global__ void scatter_kernel(const int* __restrict__ tgt) {
    int e = blockIdx.x * blockDim.x + threadIdx.x;
    if (e >= NE) return;
    int t = tgt[e];
    int p = g_off[t] + atomicAdd(&g_cur[t], 1);
    float m = ord2f(g_max[t]);
    g_eids[p] = e;
    g_exp[p]  = expf(g_scores[e] - m);
}

// ---------------- node: softmax-normalize + weighted value aggregation ----------------
__global__ void node_kernel(const float* __restrict__ value,
                            float* __restrict__ attn_out) {
    int n = (blockIdx.x << 3) + (threadIdx.x >> 5);
    if (n >= NN) return;
    int lane = threadIdx.x & 31;
    int s0 = g_off[n], s1 = g_off[n + 1];

    float ss = 0.f;
    for (int i = s0 + lane; i < s1; i += 32) ss += g_exp[i];
#pragma unroll
    for (int o = 16; o; o >>= 1) ss += __shfl_xor_sync(0xffffffffu, ss, o);
    float inv = 1.f / (ss + 1e-12f);

    float4 acc = make_float4(0.f, 0.f, 0.f, 0.f);
    const float4* V4 = reinterpret_cast<const float4*>(value);

    int i = s0;
    for (; i + 4 <= s1; i += 4) {
        int e0 = g_eids[i], e1 = g_eids[i + 1], e2 = g_eids[i + 2], e3 = g_eids[i + 3];
        float w0 = g_exp[i] * inv;
        float w1 = g_exp[i + 1] * inv;
        float w2 = g_exp[i + 2] * inv;
        float w3 = g_exp[i + 3] * inv;
        float4 v0 = V4[(size_t)e0 * 32 + lane];
        float4 v1 = V4[(size_t)e1 * 32 + lane];
        float4 v2 = V4[(size_t)e2 * 32 + lane];
        float4 v3 = V4[(size_t)e3 * 32 + lane];
        if (attn_out && lane < 4) {
            int   es = (lane == 0) ? e0 : (lane == 1) ? e1 : (lane == 2) ? e2 : e3;
            float ws = (lane == 0) ? w0 : (lane == 1) ? w1 : (lane == 2) ? w2 : w3;
            attn_out[es] = ws;
        }
        acc.x = fmaf(w0, v0.x, acc.x); acc.y = fmaf(w0, v0.y, acc.y);
        acc.z = fmaf(w0, v0.z, acc.z); acc.w = fmaf(w0, v0.w, acc.w);
        acc.x = fmaf(w1, v1.x, acc.x); acc.y = fmaf(w1, v1.y, acc.y);
        acc.z = fmaf(w1, v1.z, acc.z); acc.w = fmaf(w1, v1.w, acc.w);
        acc.x = fmaf(w2, v2.x, acc.x); acc.y = fmaf(w2, v2.y, acc.y);
        acc.z = fmaf(w2, v2.z, acc.z); acc.w = fmaf(w2, v2.w, acc.w);
        acc.x = fmaf(w3, v3.x, acc.x); acc.y = fmaf(w3, v3.y, acc.y);
        acc.z = fmaf(w3, v3.z, acc.z); acc.w = fmaf(w3, v3.w, acc.w);
    }
    for (; i < s1; i++) {
        int e = g_eids[i];
        float w = g_exp[i] * inv;
        if (attn_out && lane == 0) attn_out[e] = w;
        float4 v = V4[(size_t)e * 32 + lane];
        acc.x = fmaf(w, v.x, acc.x); acc.y = fmaf(w, v.y, acc.y);
        acc.z = fmaf(w, v.z, acc.z); acc.w = fmaf(w, v.w, acc.w);
    }
    reinterpret_cast<float4*>(g_agg)[(size_t)n * 32 + lane] = acc;
}

// ---------------- bias + LayerNorm ----------------
__global__ void ln_kernel(const float* __restrict__ bo,
                          const float* __restrict__ gamma,
                          const float* __restrict__ beta,
                          float* __restrict__ out) {
    int n = blockIdx.x;
    int j = threadIdx.x;
    int lane = j & 31, wid = j >> 5;
    __shared__ float red[4];

    float p = g_proj[n * D + j] + bo[j];
    float s = p;
#pragma unroll
    for (int o = 16; o; o >>= 1) s += __shfl_xor_sync(0xffffffffu, s, o);
    if (lane == 0) red[wid] = s;
    __syncthreads();
    float mu = (red[0] + red[1] + red[2] + red[3]) * (1.f / 128.f);
    float d = p - mu;
    float q = d * d;
    __syncthreads();
#pragma unroll
    for (int o = 16; o; o >>= 1) q += __shfl_xor_sync(0xffffffffu, q, o);
    if (lane == 0) red[wid] = q;
    __syncthreads();
    float var = (red[0] + red[1] + red[2] + red[3]) * (1.f / 128.f);
    out[n * D + j] = d * rsqrtf(var + 1e-5f) * gamma[j] + beta[j];
}

// ---------------- launch ----------------
extern "C" void kernel_launch(void* const* d_in, const int* in_sizes, int n_in,
                              void* d_out, int out_size) {
    const float* qn    = (const float*)d_in[0];
    const float* ke    = (const float*)d_in[1];
    const float* ve    = (const float*)d_in[2];
    const int*   ei    = (const int*)  d_in[3];
    const float* Wq    = (const float*)d_in[4];
    const float* Wk    = (const float*)d_in[5];
    const float* Wv    = (const float*)d_in[6];
    const float* Wo    = (const float*)d_in[7];
    const float* bo    = (const float*)d_in[8];
    const float* gamma = (const float*)d_in[9];
    const float* beta  = (const float*)d_in[10];

    const int* tgt = ei + NE;
    float* out = (float*)d_out;
    float* attn = (out_size >= NN * D + NE) ? (out + NN * D) : nullptr;

    float *p_qhat = nullptr, *p_agg = nullptr, *p_proj = nullptr;
    cudaGetSymbolAddress((void**)&p_qhat, g_qhat);
    cudaGetSymbolAddress((void**)&p_agg,  g_agg);
    cudaGetSymbolAddress((void**)&p_proj, g_proj);

    zero_counts_kernel<<<(NN + 255) / 256, 256>>>();
    combine_w_kernel<<<D, D>>>(Wq, Wk, Wv, Wo);
    gemm_tiled_kernel<<<(NN + 63) / 64, 256>>>(qn, NN, 0, p_qhat);
    scores_kernel<<<(NE / 4 + 7) / 8, 256>>>(ke, tgt);   // warp per 4 edges
    scan_kernel<<<1, 1024>>>();
    scatter_kernel<<<(NE + 255) / 256, 256>>>(tgt);
    node_kernel<<<(NN + 7) / 8, 256>>>(ve, attn);
    gemm_tiled_kernel<<<(NN + 63) / 64, 256>>>(p_agg, NN, 1, p_proj);
    ln_kernel<<<NN, 128>>>(bo, gamma, beta, out);
}